// round 10
// baseline (speedup 1.0000x reference)
#include <cuda_runtime.h>
#include <cuda_bf16.h>
#include <cuda_fp16.h>
#include <math.h>

#define N_NODES 100000
#define N_EDGES 600000
#define HID 128
#define SCAN_BLOCKS ((N_NODES + 255) / 256)          // 391
#define FILL_BLOCKS ((N_EDGES + 255) / 256)          // 2344
#define CONVX_BLOCKS ((N_NODES * 8 + 255) / 256)     // 3125
#define XF_TILES ((391 * 256) / 16)                  // 6256 (padded to grid coverage)

typedef unsigned int uint;

// ---------------- device scratch (no allocs allowed) ----------------
__device__ uint  g_Hh[(size_t)N_NODES * 64];       // h = X @ W, half2-packed
__device__ uint4 g_XF[(size_t)XF_TILES * 8 * 2 * 32]; // A-fragment-packed bf16 hi/lo input
__device__ float g_dinv[N_NODES];
__device__ float g_recip[N_NODES];
__device__ int   g_cnt[N_NODES];
__device__ int   g_fill[N_NODES];
__device__ int   g_rowptr[N_NODES + 1];
__device__ int   g_csr_src[N_EDGES];
__device__ float g_csr_w[N_EDGES];                 // dinv[s]*dinv[d] per CSR slot
__device__ float g_gate[HID];
__device__ int   g_is64;
__device__ uint  g_Wp[3][16384];                   // W frags interleaved {hi0,hi1,lo0,lo1}

__device__ __forceinline__ int edge_src(const int* ei, int e, int is64) {
    return is64 ? ei[2 * e] : ei[e];
}
__device__ __forceinline__ int edge_dst(const int* ei, int e, int is64) {
    return is64 ? ei[2 * (N_EDGES + e)] : ei[N_EDGES + e];
}

__device__ __forceinline__ void cvt_hilo(uint& hi, uint& lo, float2 v) {
    __nv_bfloat162 h = __floats2bfloat162_rn(v.x, v.y);
    __nv_bfloat162 l = __floats2bfloat162_rn(v.x - __bfloat162float(h.x),
                                             v.y - __bfloat162float(h.y));
    hi = *(uint*)&h;
    lo = *(uint*)&l;
}

// XF entry index (in uint4 units) for (row, kc, tig)
__device__ __forceinline__ size_t xf_idx(int row, int kc, int tig) {
    return ((((size_t)(row >> 4) * 8 + kc) * 2 + ((row >> 3) & 1)) * 32)
           + (row & 7) * 4 + tig;
}

// ---------------- K1: dtype detect ----------------
__global__ void detect_kernel(const int* __restrict__ ei) {
    __shared__ int any_nz;
    if (threadIdx.x == 0) any_nz = 0;
    __syncthreads();
    int local = 0;
    for (int j = threadIdx.x; j < 4096; j += 256) local |= ei[2 * j + 1];
    if (local) atomicOr(&any_nz, 1);
    __syncthreads();
    if (threadIdx.x == 0) g_is64 = (any_nz == 0) ? 1 : 0;
}

// ---------------- K2: count in-degrees ----------------
__global__ void count_kernel(const int* __restrict__ ei) {
    int e = blockIdx.x * blockDim.x + threadIdx.x;
    if (e >= N_EDGES) return;
    atomicAdd(&g_cnt[edge_dst(ei, e, g_is64)], 1);
}

// ---------------- K3: fused scan + deg + rowptr + gate + convW + convX(layer0) ----------------
__global__ void scanfuse_kernel(const float* __restrict__ x,
                                const float* __restrict__ t,
                                const float* __restrict__ Wg1, const float* __restrict__ bg1,
                                const float* __restrict__ Wg2, const float* __restrict__ bg2,
                                const float* __restrict__ W0, const float* __restrict__ W1,
                                const float* __restrict__ W2) {
    if (blockIdx.x >= SCAN_BLOCKS + 97) {
        // ---- convX: pack x into XF fragment layout ----
        int id = (blockIdx.x - (SCAN_BLOCKS + 97)) * 256 + threadIdx.x;
        int row = id >> 3, kc = id & 7;
        if (row >= N_NODES) return;
        const float4* xr = (const float4*)(x + (size_t)row * HID + kc * 16);
        float4 f0 = xr[0], f1 = xr[1], f2 = xr[2], f3 = xr[3];
        float f[16] = {f0.x, f0.y, f0.z, f0.w, f1.x, f1.y, f1.z, f1.w,
                       f2.x, f2.y, f2.z, f2.w, f3.x, f3.y, f3.z, f3.w};
        uint4* dst = g_XF + xf_idx(row, kc, 0);
#pragma unroll
        for (int tg = 0; tg < 4; tg++) {
            uint4 u;
            cvt_hilo(u.x, u.y, make_float2(f[2 * tg],     f[2 * tg + 1]));
            cvt_hilo(u.z, u.w, make_float2(f[2 * tg + 8], f[2 * tg + 9]));
            dst[tg] = u;
        }
        return;
    }
    if (blockIdx.x >= SCAN_BLOCKS) {
        int cb = blockIdx.x - SCAN_BLOCKS;
        if (cb == 96) {
            __shared__ float h1[HID];
            int j = threadIdx.x;
            if (j < HID) h1[j] = tanhf(t[0] * Wg1[j] + bg1[j]);
            __syncthreads();
            if (j < HID) {
                float s = bg2[j];
#pragma unroll 8
                for (int k = 0; k < HID; k++) s += h1[k] * Wg2[k * HID + j];
                g_gate[j] = 1.0f / (1.0f + expf(-s));
            }
            return;
        }
        int layer = cb >> 5;
        const float* W = (layer == 0) ? W0 : ((layer == 1) ? W1 : W2);
        uint* Wp = g_Wp[layer];
        int tt = (cb & 31) * 256 + threadIdx.x;
        int r = tt & 1, lane = (tt >> 1) & 31, nt = (tt >> 6) & 15, kc = tt >> 10;
        int k = kc * 16 + r * 8 + (lane & 3) * 2;
        int n = nt * 8 + (lane >> 2);
        float w0 = W[k * HID + n];
        float w1 = W[(k + 1) * HID + n];
        uint hi, lo;
        cvt_hilo(hi, lo, make_float2(w0, w1));
        int base = (tt >> 1) * 4;
        Wp[base + r]     = hi;
        Wp[base + 2 + r] = lo;
        return;
    }

    // ---- scan blocks ----
    __shared__ int sh[256];
    __shared__ int pref[256];
    int tx = threadIdx.x;
    int bid = blockIdx.x;
    int base = bid * 256;

    int local = 0;
    for (int j = tx; j < base; j += 256) local += g_cnt[j];
    pref[tx] = local;

    int i = base + tx;
    int c = (i < N_NODES) ? g_cnt[i] : 0;
    if (i < N_NODES) {
        float deg = (float)c + 1.0f;
        g_dinv[i]  = rsqrtf(deg);
        g_recip[i] = 1.0f / deg;
        g_fill[i]  = 0;
    }
    __syncthreads();
#pragma unroll
    for (int s = 128; s > 0; s >>= 1) {
        if (tx < s) pref[tx] += pref[tx + s];
        __syncthreads();
    }
    int blockoff = pref[0];

    sh[tx] = c;
    __syncthreads();
#pragma unroll
    for (int off = 1; off < 256; off <<= 1) {
        int v = (tx >= off) ? sh[tx - off] : 0;
        __syncthreads();
        sh[tx] += v;
        __syncthreads();
    }
    if (i < N_NODES) g_rowptr[i] = blockoff + sh[tx] - c;
    if (i == N_NODES - 1) g_rowptr[N_NODES] = N_EDGES;
}

// ---------------- K5: CSR fill (+ edge weights) ----------------
__global__ void fill_kernel(const int* __restrict__ ei) {
    int e = blockIdx.x * blockDim.x + threadIdx.x;
    if (e >= N_EDGES) return;
    int is64 = g_is64;
    int s = edge_src(ei, e, is64);
    int d = edge_dst(ei, e, is64);
    int pos = g_rowptr[d] + atomicAdd(&g_fill[d], 1);
    g_csr_src[pos] = s;
    g_csr_w[pos] = g_dinv[s] * g_dinv[d];
}

// ---------------- MMA helper ----------------
__device__ __forceinline__ void mma_bf16(float* c, const uint* a, const uint* b) {
    asm volatile(
        "mma.sync.aligned.m16n8k16.row.col.f32.bf16.bf16.f32 "
        "{%0,%1,%2,%3}, {%4,%5,%6,%7}, {%8,%9}, {%0,%1,%2,%3};"
        : "+f"(c[0]), "+f"(c[1]), "+f"(c[2]), "+f"(c[3])
        : "r"(a[0]), "r"(a[1]), "r"(a[2]), "r"(a[3]), "r"(b[0]), "r"(b[1]));
}

// ---------------- GEMM: Hh = XF @ W  (512 threads; warp = 32 rows x 64 cols) ----------------
__global__ __launch_bounds__(512) void gemm_mma_kernel(
    const uint4* __restrict__ XF, const uint* __restrict__ Wp,
    uint* __restrict__ Hh) {
    extern __shared__ uint smem[];
    uint* sWp = smem;   // 16384 uints = 64KB

    int tx = threadIdx.x;
#pragma unroll
    for (int i = tx; i < 4096; i += 512)
        ((uint4*)sWp)[i] = ((const uint4*)Wp)[i];
    __syncthreads();

    int warp = tx >> 5, lane = tx & 31;
    int gid = lane >> 2, tig = lane & 3;
    int colhalf = warp & 1;
    int wrow = (warp >> 1) * 32;
    int rbase = blockIdx.x * 256 + wrow;
    int rt0 = rbase >> 4;                // tile for Mtile 0; Mtile 1 = rt0+1

    float c[2][8][4];
#pragma unroll
    for (int m = 0; m < 2; m++)
#pragma unroll
        for (int j = 0; j < 8; j++)
#pragma unroll
            for (int r = 0; r < 4; r++) c[m][j][r] = 0.f;

#pragma unroll
    for (int kc = 0; kc < 8; kc++) {
        uint ah[2][4], al[2][4];
#pragma unroll
        for (int m = 0; m < 2; m++) {
            size_t tb = ((size_t)(rt0 + m) * 8 + kc) * 2;
            uint4 u = XF[(tb + 0) * 32 + lane];
            uint4 v = XF[(tb + 1) * 32 + lane];
            ah[m][0] = u.x; ah[m][1] = v.x; ah[m][2] = u.z; ah[m][3] = v.z;
            al[m][0] = u.y; al[m][1] = v.y; al[m][2] = u.w; al[m][3] = v.w;
        }
        const uint* wp = sWp + ((kc * 16 + colhalf * 8) * 32 + lane) * 4;
#pragma unroll
        for (int j = 0; j < 8; j++) {
            uint4 w = *(const uint4*)(wp + j * 128);
            uint bh[2] = {w.x, w.y};
            uint bl[2] = {w.z, w.w};
#pragma unroll
            for (int m = 0; m < 2; m++) {
                mma_bf16(c[m][j], ah[m], bh);
                mma_bf16(c[m][j], ah[m], bl);
                mma_bf16(c[m][j], al[m], bh);
            }
        }
    }

#pragma unroll
    for (int m = 0; m < 2; m++) {
        int rg  = rbase + m * 16 + gid;
        int rg8 = rg + 8;
        bool v0 = rg < N_NODES, v8 = rg8 < N_NODES;
#pragma unroll
        for (int j = 0; j < 8; j++) {
            int colh = colhalf * 32 + j * 4 + tig;   // half2 column index
            if (v0) {
                __half2 p = __floats2half2_rn(c[m][j][0], c[m][j][1]);
                Hh[(size_t)rg * 64 + colh] = *(uint*)&p;
            }
            if (v8) {
                __half2 p = __floats2half2_rn(c[m][j][2], c[m][j][3]);
                Hh[(size_t)rg8 * 64 + colh] = *(uint*)&p;
            }
        }
    }
}

// ---------------- CSR gather: acc = sum H[s]*w + H[d]*recip + b; act; write XF or out ----------------
template <int FINAL>
__global__ __launch_bounds__(256) void gather_kernel(const uint* __restrict__ Hh,
                                                     const float* __restrict__ b,
                                                     float* __restrict__ out) {
    int gtid = blockIdx.x * blockDim.x + threadIdx.x;
    int d = gtid >> 5;
    int lane = threadIdx.x & 31;
    if (d >= N_NODES) return;

    int beg = g_rowptr[d];
    int end = g_rowptr[d + 1];

    float rc = g_recip[d];
    uint2 hv = ((const uint2*)(Hh + (size_t)d * 64))[lane];
    float2 a0 = __half22float2(*(__half2*)&hv.x);
    float2 a1 = __half22float2(*(__half2*)&hv.y);
    float4 acc0 = make_float4(a0.x * rc, a0.y * rc, a1.x * rc, a1.y * rc);
    float4 acc1 = make_float4(0.f, 0.f, 0.f, 0.f);

    int e = beg;
    for (; e + 1 < end; e += 2) {
        int s0 = g_csr_src[e];
        int s1 = g_csr_src[e + 1];
        float w0 = g_csr_w[e];
        float w1 = g_csr_w[e + 1];
        uint2 r0 = ((const uint2*)(Hh + (size_t)s0 * 64))[lane];
        uint2 r1 = ((const uint2*)(Hh + (size_t)s1 * 64))[lane];
        float2 h00 = __half22float2(*(__half2*)&r0.x);
        float2 h01 = __half22float2(*(__half2*)&r0.y);
        float2 h10 = __half22float2(*(__half2*)&r1.x);
        float2 h11 = __half22float2(*(__half2*)&r1.y);
        acc0.x += h00.x * w0; acc0.y += h00.y * w0; acc0.z += h01.x * w0; acc0.w += h01.y * w0;
        acc1.x += h10.x * w1; acc1.y += h10.y * w1; acc1.z += h11.x * w1; acc1.w += h11.y * w1;
    }
    if (e < end) {
        int s0 = g_csr_src[e];
        float w0 = g_csr_w[e];
        uint2 r0 = ((const uint2*)(Hh + (size_t)s0 * 64))[lane];
        float2 h00 = __half22float2(*(__half2*)&r0.x);
        float2 h01 = __half22float2(*(__half2*)&r0.y);
        acc0.x += h00.x * w0; acc0.y += h00.y * w0; acc0.z += h01.x * w0; acc0.w += h01.y * w0;
    }

    float4 bv = ((const float4*)b)[lane];
    float4 g = ((const float4*)g_gate)[lane];
    float4 o;
    o.x = acc0.x + acc1.x + bv.x;
    o.y = acc0.y + acc1.y + bv.y;
    o.z = acc0.z + acc1.z + bv.z;
    o.w = acc0.w + acc1.w + bv.w;

    if (FINAL) {
        o.x = fmaxf(o.x, 0.f) * g.x;
        o.y = fmaxf(o.y, 0.f) * g.y;
        o.z = fmaxf(o.z, 0.f) * g.z;
        o.w = fmaxf(o.w, 0.f) * g.w;
        ((float4*)(out + (size_t)d * HID))[lane] = o;
    } else {
        // apply act here (moved out of GEMM), write fragment-packed XF
        o.x = fmaxf(o.x, 0.f) * g.x;
        o.y = fmaxf(o.y, 0.f) * g.y;
        o.z = fmaxf(o.z, 0.f) * g.z;
        o.w = fmaxf(o.w, 0.f) * g.w;
        int kc  = lane >> 2;
        int rr  = (lane << 2) & 15;          // 0,4,8,12
        int tgA = (rr >> 1) & 3;             // 0 or 2
        int off = (rr >= 8) ? 2 : 0;         // xy vs zw
        uint hiA, loA, hiB, loB;
        cvt_hilo(hiA, loA, make_float2(o.x, o.y));
        cvt_hilo(hiB, loB, make_float2(o.z, o.w));
        uint* p = (uint*)(g_XF + (xf_idx(d, kc, 0)));
        *(uint2*)(p + tgA * 4 + off)       = make_uint2(hiA, loA);
        *(uint2*)(p + (tgA + 1) * 4 + off) = make_uint2(hiB, loB);
    }
}

// ---------------- launch ----------------
extern "C" void kernel_launch(void* const* d_in, const int* in_sizes, int n_in,
                              void* d_out, int out_size) {
    const float* x   = (const float*)d_in[0];
    const int*   ei  = (const int*)d_in[1];
    const float* ts  = (const float*)d_in[2];
    const float* W0  = (const float*)d_in[3];
    const float* b0  = (const float*)d_in[4];
    const float* W1  = (const float*)d_in[5];
    const float* b1  = (const float*)d_in[6];
    const float* W2  = (const float*)d_in[7];
    const float* b2  = (const float*)d_in[8];
    const float* Wg1 = (const float*)d_in[9];
    const float* bg1 = (const float*)d_in[10];
    const float* Wg2 = (const float*)d_in[11];
    const float* bg2 = (const float*)d_in[12];
    float* out = (float*)d_out;

    const int SMEM = 16384 * 4;   // 64KB
    cudaFuncSetAttribute(gemm_mma_kernel, cudaFuncAttributeMaxDynamicSharedMemorySize, SMEM);

    uint *Hh, *Wp;
    uint4 *XF;
    int  *cnt;
    cudaGetSymbolAddress((void**)&Hh,  g_Hh);
    cudaGetSymbolAddress((void**)&XF,  g_XF);
    cudaGetSymbolAddress((void**)&Wp,  g_Wp);
    cudaGetSymbolAddress((void**)&cnt, g_cnt);

    const int gemm_blocks = (N_NODES + 255) / 256;    // 391
    const int gath_blocks = (N_NODES * 32 + 255) / 256;

    cudaMemsetAsync(cnt, 0, N_NODES * sizeof(int), 0);
    detect_kernel<<<1, 256>>>(ei);
    count_kernel<<<FILL_BLOCKS, 256>>>(ei);
    scanfuse_kernel<<<SCAN_BLOCKS + 97 + CONVX_BLOCKS, 256>>>(
        x, ts, Wg1, bg1, Wg2, bg2, W0, W1, W2);
    gemm_mma_kernel<<<gemm_blocks, 512, SMEM>>>(XF, Wp, Hh);            // profiled
    fill_kernel<<<FILL_BLOCKS, 256>>>(ei);
    gather_kernel<0><<<gath_blocks, 256>>>(Hh, b0, out);
    gemm_mma_kernel<<<gemm_blocks, 512, SMEM>>>(XF, Wp + 16384, Hh);
    gather_kernel<0><<<gath_blocks, 256>>>(Hh, b1, out);
    gemm_mma_kernel<<<gemm_blocks, 512, SMEM>>>(XF, Wp + 32768, Hh);
    gather_kernel<1><<<gath_blocks, 256>>>(Hh, b2, out);
}

// round 11
// speedup vs baseline: 1.1165x; 1.1165x over previous
#include <cuda_runtime.h>
#include <cuda_bf16.h>
#include <cuda_fp16.h>
#include <math.h>

#define N_NODES 100000
#define N_EDGES 600000
#define HID 128
#define SCAN_BLOCKS ((N_NODES + 255) / 256)   // 391
#define FILL_BLOCKS ((N_EDGES + 255) / 256)   // 2344

typedef unsigned int uint;

// ---------------- device scratch (no allocs allowed) ----------------
__device__ uint  g_Hh[(size_t)N_NODES * 64];   // h = X @ W, half2-packed (64 half2 per row)
__device__ float g_A[(size_t)N_NODES * HID];   // layer output (fp32)
__device__ float g_dinv[N_NODES];
__device__ float g_recip[N_NODES];
__device__ int   g_cnt[N_NODES];
__device__ int   g_fill[N_NODES];
__device__ int   g_rowptr[N_NODES + 1];
__device__ int   g_csr_src[N_EDGES];
__device__ float g_csr_w[N_EDGES];
__device__ float g_gate[HID];
__device__ int   g_is64;
__device__ uint  g_Wp[3][16384];               // W frags interleaved {hi0,hi1,lo0,lo1}

__device__ __forceinline__ int edge_src(const int* ei, int e, int is64) {
    return is64 ? ei[2 * e] : ei[e];
}
__device__ __forceinline__ int edge_dst(const int* ei, int e, int is64) {
    return is64 ? ei[2 * (N_EDGES + e)] : ei[N_EDGES + e];
}

__device__ __forceinline__ void cvt_hilo(uint& hi, uint& lo, float2 v) {
    __nv_bfloat162 h = __floats2bfloat162_rn(v.x, v.y);
    __nv_bfloat162 l = __floats2bfloat162_rn(v.x - __bfloat162float(h.x),
                                             v.y - __bfloat162float(h.y));
    hi = *(uint*)&h;
    lo = *(uint*)&l;
}

// ---------------- K1: dtype detect ----------------
__global__ void detect_kernel(const int* __restrict__ ei) {
    __shared__ int any_nz;
    if (threadIdx.x == 0) any_nz = 0;
    __syncthreads();
    int local = 0;
    for (int j = threadIdx.x; j < 4096; j += 256) local |= ei[2 * j + 1];
    if (local) atomicOr(&any_nz, 1);
    __syncthreads();
    if (threadIdx.x == 0) g_is64 = (any_nz == 0) ? 1 : 0;
}

// ---------------- K2: count in-degrees ----------------
__global__ void count_kernel(const int* __restrict__ ei) {
    int e = blockIdx.x * blockDim.x + threadIdx.x;
    if (e >= N_EDGES) return;
    atomicAdd(&g_cnt[edge_dst(ei, e, g_is64)], 1);
}

// ---------------- K3: fused scan + deg + rowptr + gate + convW ----------------
__global__ void scanfuse_kernel(const float* __restrict__ t,
                                const float* __restrict__ Wg1, const float* __restrict__ bg1,
                                const float* __restrict__ Wg2, const float* __restrict__ bg2,
                                const float* __restrict__ W0, const float* __restrict__ W1,
                                const float* __restrict__ W2) {
    if (blockIdx.x >= SCAN_BLOCKS) {
        int cb = blockIdx.x - SCAN_BLOCKS;
        if (cb == 96) {
            __shared__ float h1[HID];
            int j = threadIdx.x;
            if (j < HID) h1[j] = tanhf(t[0] * Wg1[j] + bg1[j]);
            __syncthreads();
            if (j < HID) {
                float s = bg2[j];
#pragma unroll 8
                for (int k = 0; k < HID; k++) s += h1[k] * Wg2[k * HID + j];
                g_gate[j] = 1.0f / (1.0f + expf(-s));
            }
            return;
        }
        int layer = cb >> 5;
        const float* W = (layer == 0) ? W0 : ((layer == 1) ? W1 : W2);
        uint* Wp = g_Wp[layer];
        int tt = (cb & 31) * 256 + threadIdx.x;
        int r = tt & 1, lane = (tt >> 1) & 31, nt = (tt >> 6) & 15, kc = tt >> 10;
        int k = kc * 16 + r * 8 + (lane & 3) * 2;
        int n = nt * 8 + (lane >> 2);
        float w0 = W[k * HID + n];
        float w1 = W[(k + 1) * HID + n];
        uint hi, lo;
        cvt_hilo(hi, lo, make_float2(w0, w1));
        int base = (tt >> 1) * 4;
        Wp[base + r]     = hi;
        Wp[base + 2 + r] = lo;
        return;
    }

    __shared__ int sh[256];
    __shared__ int pref[256];
    int tx = threadIdx.x;
    int bid = blockIdx.x;
    int base = bid * 256;

    int local = 0;
    for (int j = tx; j < base; j += 256) local += g_cnt[j];
    pref[tx] = local;

    int i = base + tx;
    int c = (i < N_NODES) ? g_cnt[i] : 0;
    if (i < N_NODES) {
        float deg = (float)c + 1.0f;
        g_dinv[i]  = rsqrtf(deg);
        g_recip[i] = 1.0f / deg;
        g_fill[i]  = 0;
    }
    __syncthreads();
#pragma unroll
    for (int s = 128; s > 0; s >>= 1) {
        if (tx < s) pref[tx] += pref[tx + s];
        __syncthreads();
    }
    int blockoff = pref[0];

    sh[tx] = c;
    __syncthreads();
#pragma unroll
    for (int off = 1; off < 256; off <<= 1) {
        int v = (tx >= off) ? sh[tx - off] : 0;
        __syncthreads();
        sh[tx] += v;
        __syncthreads();
    }
    if (i < N_NODES) g_rowptr[i] = blockoff + sh[tx] - c;
    if (i == N_NODES - 1) g_rowptr[N_NODES] = N_EDGES;
}

// ---------------- K5: CSR fill (+ edge weights) ----------------
__global__ void fill_kernel(const int* __restrict__ ei) {
    int e = blockIdx.x * blockDim.x + threadIdx.x;
    if (e >= N_EDGES) return;
    int is64 = g_is64;
    int s = edge_src(ei, e, is64);
    int d = edge_dst(ei, e, is64);
    int pos = g_rowptr[d] + atomicAdd(&g_fill[d], 1);
    g_csr_src[pos] = s;
    g_csr_w[pos] = g_dinv[s] * g_dinv[d];
}

// ---------------- MMA helpers ----------------
__device__ __forceinline__ void mma_bf16(float* c, const uint* a, const uint* b) {
    asm volatile(
        "mma.sync.aligned.m16n8k16.row.col.f32.bf16.bf16.f32 "
        "{%0,%1,%2,%3}, {%4,%5,%6,%7}, {%8,%9}, {%0,%1,%2,%3};"
        : "+f"(c[0]), "+f"(c[1]), "+f"(c[2]), "+f"(c[3])
        : "r"(a[0]), "r"(a[1]), "r"(a[2]), "r"(a[3]), "r"(b[0]), "r"(b[1]));
}

template <int ACT>
__device__ __forceinline__ void load_frag(uint& hi, uint& lo, const float* base,
                                          int k, bool valid, const float* sg) {
    float2 v = valid ? *(const float2*)(base + k) : make_float2(0.f, 0.f);
    if (ACT) {
        v.x = fmaxf(v.x, 0.f) * sg[k];
        v.y = fmaxf(v.y, 0.f) * sg[k + 1];
    }
    __nv_bfloat162 h = __floats2bfloat162_rn(v.x, v.y);
    __nv_bfloat162 l = __floats2bfloat162_rn(v.x - __bfloat162float(h.x),
                                             v.y - __bfloat162float(h.y));
    hi = *(uint*)&h;
    lo = *(uint*)&l;
}

// ---------------- GEMM: Hh = act(Xin) @ W  (512 thr; warp = 32 rows x 64 cols) ----------------
// B-fragments shared across 2 M-tiles -> half the LDS.128 traffic of the 16x128 tile.
template <int ACT>
__global__ __launch_bounds__(512) void gemm_mma_kernel(
    const float* __restrict__ Xin, const uint* __restrict__ Wp,
    uint* __restrict__ Hh) {
    extern __shared__ uint smem[];
    uint* sWp = smem;                       // 16384 uints = 64KB
    float* sg = (float*)(smem + 16384);

    int tx = threadIdx.x;
#pragma unroll
    for (int i = tx; i < 4096; i += 512)
        ((uint4*)sWp)[i] = ((const uint4*)Wp)[i];
    if (ACT && tx < HID) sg[tx] = g_gate[tx];
    __syncthreads();

    int warp = tx >> 5, lane = tx & 31;
    int gid = lane >> 2, tig = lane & 3;
    int colhalf = warp & 1;
    int rbase = blockIdx.x * 256 + (warp >> 1) * 32;
    int r0 = rbase + gid;
    int r1 = r0 + 8, r2 = r0 + 16, r3 = r0 + 24;
    bool v0 = r0 < N_NODES, v1 = r1 < N_NODES, v2 = r2 < N_NODES, v3 = r3 < N_NODES;
    const float* X0 = Xin + (size_t)r0 * HID;
    const float* X1 = Xin + (size_t)r1 * HID;
    const float* X2 = Xin + (size_t)r2 * HID;
    const float* X3 = Xin + (size_t)r3 * HID;

    float c[2][8][4];
#pragma unroll
    for (int m = 0; m < 2; m++)
#pragma unroll
        for (int j = 0; j < 8; j++)
#pragma unroll
            for (int r = 0; r < 4; r++) c[m][j][r] = 0.f;

#pragma unroll
    for (int kc = 0; kc < 8; kc++) {
        int k0 = kc * 16 + tig * 2;
        uint ah[2][4], al[2][4];
        load_frag<ACT>(ah[0][0], al[0][0], X0, k0,     v0, sg);
        load_frag<ACT>(ah[0][1], al[0][1], X1, k0,     v1, sg);
        load_frag<ACT>(ah[0][2], al[0][2], X0, k0 + 8, v0, sg);
        load_frag<ACT>(ah[0][3], al[0][3], X1, k0 + 8, v1, sg);
        load_frag<ACT>(ah[1][0], al[1][0], X2, k0,     v2, sg);
        load_frag<ACT>(ah[1][1], al[1][1], X3, k0,     v3, sg);
        load_frag<ACT>(ah[1][2], al[1][2], X2, k0 + 8, v2, sg);
        load_frag<ACT>(ah[1][3], al[1][3], X3, k0 + 8, v3, sg);

        const uint* wp = sWp + ((kc * 16 + colhalf * 8) * 32 + lane) * 4;
#pragma unroll
        for (int j = 0; j < 8; j++) {
            uint4 w = *(const uint4*)(wp + j * 128);
            uint bh[2] = {w.x, w.y};
            uint bl[2] = {w.z, w.w};
#pragma unroll
            for (int m = 0; m < 2; m++) {
                mma_bf16(c[m][j], ah[m], bh);
                mma_bf16(c[m][j], ah[m], bl);
                mma_bf16(c[m][j], al[m], bh);
            }
        }
    }

#pragma unroll
    for (int m = 0; m < 2; m++) {
        int rg  = rbase + m * 16 + gid;
        int rg8 = rg + 8;
        bool w0 = rg < N_NODES, w8 = rg8 < N_NODES;
#pragma unroll
        for (int j = 0; j < 8; j++) {
            int colh = colhalf * 32 + j * 4 + tig;   // half2 column index
            if (w0) {
                __half2 p = __floats2half2_rn(c[m][j][0], c[m][j][1]);
                Hh[(size_t)rg * 64 + colh] = *(uint*)&p;
            }
            if (w8) {
                __half2 p = __floats2half2_rn(c[m][j][2], c[m][j][3]);
                Hh[(size_t)rg8 * 64 + colh] = *(uint*)&p;
            }
        }
    }
}

// ---------------- CSR gather (fp16 rows): A[d] = sum H[s]*w + H[d]*recip + b ----------------
template <int FINAL>
__global__ __launch_bounds__(256) void gather_kernel(const uint* __restrict__ Hh,
                                                     const float* __restrict__ b,
                                                     float* __restrict__ A) {
    int gtid = blockIdx.x * blockDim.x + threadIdx.x;
    int d = gtid >> 5;
    int lane = threadIdx.x & 31;
    if (d >= N_NODES) return;

    int beg = g_rowptr[d];
    int end = g_rowptr[d + 1];

    float rc = g_recip[d];
    uint2 hv = ((const uint2*)(Hh + (size_t)d * 64))[lane];
    float2 a0 = __half22float2(*(__half2*)&hv.x);
    float2 a1 = __half22float2(*(__half2*)&hv.y);
    float4 acc0 = make_float4(a0.x * rc, a0.y * rc, a1.x * rc, a1.y * rc);
    float4 acc1 = make_float4(0.f, 0.f, 0.f, 0.f);

    int e = beg;
    for (; e + 1 < end; e += 2) {
        int s0 = g_csr_src[e];
        int s1 = g_csr_src[e + 1];
        float w0 = g_csr_w[e];
        float w1 = g_csr_w[e + 1];
        uint2 r0 = ((const uint2*)(Hh + (size_t)s0 * 64))[lane];
        uint2 r1 = ((const uint2*)(Hh + (size_t)s1 * 64))[lane];
        float2 h00 = __half22float2(*(__half2*)&r0.x);
        float2 h01 = __half22float2(*(__half2*)&r0.y);
        float2 h10 = __half22float2(*(__half2*)&r1.x);
        float2 h11 = __half22float2(*(__half2*)&r1.y);
        acc0.x += h00.x * w0; acc0.y += h00.y * w0; acc0.z += h01.x * w0; acc0.w += h01.y * w0;
        acc1.x += h10.x * w1; acc1.y += h10.y * w1; acc1.z += h11.x * w1; acc1.w += h11.y * w1;
    }
    if (e < end) {
        int s0 = g_csr_src[e];
        float w0 = g_csr_w[e];
        uint2 r0 = ((const uint2*)(Hh + (size_t)s0 * 64))[lane];
        float2 h00 = __half22float2(*(__half2*)&r0.x);
        float2 h01 = __half22float2(*(__half2*)&r0.y);
        acc0.x += h00.x * w0; acc0.y += h00.y * w0; acc0.z += h01.x * w0; acc0.w += h01.y * w0;
    }

    float4 bv = ((const float4*)b)[lane];
    float4 o;
    o.x = acc0.x + acc1.x + bv.x;
    o.y = acc0.y + acc1.y + bv.y;
    o.z = acc0.z + acc1.z + bv.z;
    o.w = acc0.w + acc1.w + bv.w;

    if (FINAL) {
        float4 g = ((const float4*)g_gate)[lane];
        o.x = fmaxf(o.x, 0.f) * g.x;
        o.y = fmaxf(o.y, 0.f) * g.y;
        o.z = fmaxf(o.z, 0.f) * g.z;
        o.w = fmaxf(o.w, 0.f) * g.w;
    }
    ((float4*)(A + (size_t)d * HID))[lane] = o;
}

// ---------------- launch ----------------
extern "C" void kernel_launch(void* const* d_in, const int* in_sizes, int n_in,
                              void* d_out, int out_size) {
    const float* x   = (const float*)d_in[0];
    const int*   ei  = (const int*)d_in[1];
    const float* ts  = (const float*)d_in[2];
    const float* W0  = (const float*)d_in[3];
    const float* b0  = (const float*)d_in[4];
    const float* W1  = (const float*)d_in[5];
    const float* b1  = (const float*)d_in[6];
    const float* W2  = (const float*)d_in[7];
    const float* b2  = (const float*)d_in[8];
    const float* Wg1 = (const float*)d_in[9];
    const float* bg1 = (const float*)d_in[10];
    const float* Wg2 = (const float*)d_in[11];
    const float* bg2 = (const float*)d_in[12];
    float* out = (float*)d_out;

    const int SMEM = 16384 * 4 + 512;
    cudaFuncSetAttribute(gemm_mma_kernel<0>, cudaFuncAttributeMaxDynamicSharedMemorySize, SMEM);
    cudaFuncSetAttribute(gemm_mma_kernel<1>, cudaFuncAttributeMaxDynamicSharedMemorySize, SMEM);

    float *A;
    uint *Hh, *Wp;
    int  *cnt;
    cudaGetSymbolAddress((void**)&Hh,  g_Hh);
    cudaGetSymbolAddress((void**)&A,   g_A);
    cudaGetSymbolAddress((void**)&Wp,  g_Wp);
    cudaGetSymbolAddress((void**)&cnt, g_cnt);

    const int gemm_blocks = (N_NODES + 255) / 256;
    const int gath_blocks = (N_NODES * 32 + 255) / 256;

    cudaMemsetAsync(cnt, 0, N_NODES * sizeof(int), 0);
    detect_kernel<<<1, 256>>>(ei);
    count_kernel<<<FILL_BLOCKS, 256>>>(ei);
    scanfuse_kernel<<<SCAN_BLOCKS + 97, 256>>>(ts, Wg1, bg1, Wg2, bg2, W0, W1, W2);
    gemm_mma_kernel<0><<<gemm_blocks, 512, SMEM>>>(x, Wp, Hh);              // profiled
    fill_kernel<<<FILL_BLOCKS, 256>>>(ei);
    gather_kernel<0><<<gath_blocks, 256>>>(Hh, b0, A);
    gemm_mma_kernel<1><<<gemm_blocks, 512, SMEM>>>(A, Wp + 16384, Hh);
    gather_kernel<0><<<gath_blocks, 256>>>(Hh, b1, A);
    gemm_mma_kernel<1><<<gemm_blocks, 512, SMEM>>>(A, Wp + 32768, Hh);
    gather_kernel<1><<<gath_blocks, 256>>>(Hh, b2, out);
}

// round 12
// speedup vs baseline: 1.1745x; 1.0520x over previous
#include <cuda_runtime.h>
#include <cuda_fp16.h>
#include <math.h>

#define N_NODES 100000
#define PAD_ROWS 100096                        // 391*256 grid coverage
#define N_EDGES 600000
#define HID 128
#define SCAN_BLOCKS ((N_NODES + 255) / 256)    // 391
#define FILL_BLOCKS ((N_EDGES + 255) / 256)    // 2344
#define CONVX_BLOCKS ((PAD_ROWS * 8 + 255) / 256)

typedef unsigned int uint;

// ---------------- device scratch (no allocs allowed) ----------------
__device__ uint  g_Hh[(size_t)N_NODES * 64];    // H = X @ W, half2-packed
__device__ uint  g_Xh[(size_t)PAD_ROWS * 64];   // GEMM input, half2-packed (x, then act(A))
__device__ float g_dinv[N_NODES];
__device__ float g_recip[N_NODES];
__device__ int   g_cnt[N_NODES];
__device__ int   g_fill[N_NODES];
__device__ int   g_rowptr[N_NODES + 1];
__device__ int   g_csr_src[N_EDGES];
__device__ float g_csr_w[N_EDGES];
__device__ float g_gate[HID];
__device__ int   g_is64;
__device__ uint  g_Wp[3][16384];                // W frags fp16, interleaved {hi0,hi1,lo0,lo1}

__device__ __forceinline__ int edge_src(const int* ei, int e, int is64) {
    return is64 ? ei[2 * e] : ei[e];
}
__device__ __forceinline__ int edge_dst(const int* ei, int e, int is64) {
    return is64 ? ei[2 * (N_EDGES + e)] : ei[N_EDGES + e];
}

__device__ __forceinline__ void cvt_hilo_h(uint& hi, uint& lo, float2 v) {
    __half2 h = __floats2half2_rn(v.x, v.y);
    float hx = __half2float(__low2half(h));
    float hy = __half2float(__high2half(h));
    __half2 l = __floats2half2_rn(v.x - hx, v.y - hy);
    hi = *(uint*)&h;
    lo = *(uint*)&l;
}

// ---------------- K1: dtype detect ----------------
__global__ void detect_kernel(const int* __restrict__ ei) {
    __shared__ int any_nz;
    if (threadIdx.x == 0) any_nz = 0;
    __syncthreads();
    int local = 0;
    for (int j = threadIdx.x; j < 4096; j += 256) local |= ei[2 * j + 1];
    if (local) atomicOr(&any_nz, 1);
    __syncthreads();
    if (threadIdx.x == 0) g_is64 = (any_nz == 0) ? 1 : 0;
}

// ---------------- K2: count in-degrees ----------------
__global__ void count_kernel(const int* __restrict__ ei) {
    int e = blockIdx.x * blockDim.x + threadIdx.x;
    if (e >= N_EDGES) return;
    atomicAdd(&g_cnt[edge_dst(ei, e, g_is64)], 1);
}

// ---------------- K3: fused scan + deg + rowptr + gate + convW + convX ----------------
__global__ void scanfuse_kernel(const float* __restrict__ x,
                                const float* __restrict__ t,
                                const float* __restrict__ Wg1, const float* __restrict__ bg1,
                                const float* __restrict__ Wg2, const float* __restrict__ bg2,
                                const float* __restrict__ W0, const float* __restrict__ W1,
                                const float* __restrict__ W2) {
    if (blockIdx.x >= SCAN_BLOCKS + 97) {
        // ---- convX: pack x rows into half2 (zero-pad rows >= N_NODES) ----
        int id = (blockIdx.x - (SCAN_BLOCKS + 97)) * 256 + threadIdx.x;
        int row = id >> 3, seg = id & 7;
        if (row >= PAD_ROWS) return;
        uint4 u0, u1;
        if (row < N_NODES) {
            const float4* xr = (const float4*)(x + (size_t)row * HID + seg * 16);
            float4 f0 = xr[0], f1 = xr[1], f2 = xr[2], f3 = xr[3];
            __half2 h0 = __floats2half2_rn(f0.x, f0.y), h1 = __floats2half2_rn(f0.z, f0.w);
            __half2 h2 = __floats2half2_rn(f1.x, f1.y), h3 = __floats2half2_rn(f1.z, f1.w);
            __half2 h4 = __floats2half2_rn(f2.x, f2.y), h5 = __floats2half2_rn(f2.z, f2.w);
            __half2 h6 = __floats2half2_rn(f3.x, f3.y), h7 = __floats2half2_rn(f3.z, f3.w);
            u0 = make_uint4(*(uint*)&h0, *(uint*)&h1, *(uint*)&h2, *(uint*)&h3);
            u1 = make_uint4(*(uint*)&h4, *(uint*)&h5, *(uint*)&h6, *(uint*)&h7);
        } else {
            u0 = make_uint4(0, 0, 0, 0);
            u1 = make_uint4(0, 0, 0, 0);
        }
        uint4* dst = (uint4*)(g_Xh + (size_t)row * 64 + seg * 8);
        dst[0] = u0;
        dst[1] = u1;
        return;
    }
    if (blockIdx.x >= SCAN_BLOCKS) {
        int cb = blockIdx.x - SCAN_BLOCKS;
        if (cb == 96) {
            __shared__ float h1s[HID];
            int j = threadIdx.x;
            if (j < HID) h1s[j] = tanhf(t[0] * Wg1[j] + bg1[j]);
            __syncthreads();
            if (j < HID) {
                float s = bg2[j];
#pragma unroll 8
                for (int k = 0; k < HID; k++) s += h1s[k] * Wg2[k * HID + j];
                g_gate[j] = 1.0f / (1.0f + expf(-s));
            }
            return;
        }
        int layer = cb >> 5;
        const float* W = (layer == 0) ? W0 : ((layer == 1) ? W1 : W2);
        uint* Wp = g_Wp[layer];
        int tt = (cb & 31) * 256 + threadIdx.x;
        int r = tt & 1, lane = (tt >> 1) & 31, nt = (tt >> 6) & 15, kc = tt >> 10;
        int k = kc * 16 + r * 8 + (lane & 3) * 2;
        int n = nt * 8 + (lane >> 2);
        float w0 = W[k * HID + n];
        float w1 = W[(k + 1) * HID + n];
        uint hi, lo;
        cvt_hilo_h(hi, lo, make_float2(w0, w1));
        int base = (tt >> 1) * 4;
        Wp[base + r]     = hi;
        Wp[base + 2 + r] = lo;
        return;
    }

    // ---- scan blocks ----
    __shared__ int sh[256];
    __shared__ int pref[256];
    int tx = threadIdx.x;
    int bid = blockIdx.x;
    int base = bid * 256;

    int local = 0;
    for (int j = tx; j < base; j += 256) local += g_cnt[j];
    pref[tx] = local;

    int i = base + tx;
    int c = (i < N_NODES) ? g_cnt[i] : 0;
    if (i < N_NODES) {
        float deg = (float)c + 1.0f;
        g_dinv[i]  = rsqrtf(deg);
        g_recip[i] = 1.0f / deg;
        g_fill[i]  = 0;
    }
    __syncthreads();
#pragma unroll
    for (int s = 128; s > 0; s >>= 1) {
        if (tx < s) pref[tx] += pref[tx + s];
        __syncthreads();
    }
    int blockoff = pref[0];

    sh[tx] = c;
    __syncthreads();
#pragma unroll
    for (int off = 1; off < 256; off <<= 1) {
        int v = (tx >= off) ? sh[tx - off] : 0;
        __syncthreads();
        sh[tx] += v;
        __syncthreads();
    }
    if (i < N_NODES) g_rowptr[i] = blockoff + sh[tx] - c;
    if (i == N_NODES - 1) g_rowptr[N_NODES] = N_EDGES;
}

// ---------------- K5: CSR fill (+ edge weights) ----------------
__global__ void fill_kernel(const int* __restrict__ ei) {
    int e = blockIdx.x * blockDim.x + threadIdx.x;
    if (e >= N_EDGES) return;
    int is64 = g_is64;
    int s = edge_src(ei, e, is64);
    int d = edge_dst(ei, e, is64);
    int pos = g_rowptr[d] + atomicAdd(&g_fill[d], 1);
    g_csr_src[pos] = s;
    g_csr_w[pos] = g_dinv[s] * g_dinv[d];
}

// ---------------- MMA helper (f16 inputs, f32 accum) ----------------
__device__ __forceinline__ void mma_f16(float* c, const uint* a, const uint* b) {
    asm volatile(
        "mma.sync.aligned.m16n8k16.row.col.f32.f16.f16.f32 "
        "{%0,%1,%2,%3}, {%4,%5,%6,%7}, {%8,%9}, {%0,%1,%2,%3};"
        : "+f"(c[0]), "+f"(c[1]), "+f"(c[2]), "+f"(c[3])
        : "r"(a[0]), "r"(a[1]), "r"(a[2]), "r"(a[3]), "r"(b[0]), "r"(b[1]));
}

// ---------------- GEMM: Hh = Xh @ W  (512 thr; warp = 32 rows x 64 cols; fp16 A raw) ----------------
__global__ __launch_bounds__(512) void gemm_mma_kernel(
    const uint* __restrict__ Xh, const uint* __restrict__ Wp,
    uint* __restrict__ Hh) {
    extern __shared__ uint smem[];
    uint* sWp = smem;   // 16384 uints = 64KB

    int tx = threadIdx.x;
#pragma unroll
    for (int i = tx; i < 4096; i += 512)
        ((uint4*)sWp)[i] = ((const uint4*)Wp)[i];
    __syncthreads();

    int warp = tx >> 5, lane = tx & 31;
    int gid = lane >> 2, tig = lane & 3;
    int colhalf = warp & 1;
    int rbase = blockIdx.x * 256 + (warp >> 1) * 32;
    const uint* Xr0 = Xh + (size_t)(rbase + gid)      * 64;
    const uint* Xr1 = Xh + (size_t)(rbase + gid + 8)  * 64;
    const uint* Xr2 = Xh + (size_t)(rbase + gid + 16) * 64;
    const uint* Xr3 = Xh + (size_t)(rbase + gid + 24) * 64;

    float c[2][8][4];
#pragma unroll
    for (int m = 0; m < 2; m++)
#pragma unroll
        for (int j = 0; j < 8; j++)
#pragma unroll
            for (int r = 0; r < 4; r++) c[m][j][r] = 0.f;

#pragma unroll
    for (int kc = 0; kc < 8; kc++) {
        int i0 = kc * 8 + tig;           // half2 index of k-pair (tig*2, tig*2+1)
        uint a[2][4];
        a[0][0] = Xr0[i0];     a[0][1] = Xr1[i0];
        a[0][2] = Xr0[i0 + 4]; a[0][3] = Xr1[i0 + 4];
        a[1][0] = Xr2[i0];     a[1][1] = Xr3[i0];
        a[1][2] = Xr2[i0 + 4]; a[1][3] = Xr3[i0 + 4];

        const uint* wp = sWp + ((kc * 16 + colhalf * 8) * 32 + lane) * 4;
#pragma unroll
        for (int j = 0; j < 8; j++) {
            uint4 w = *(const uint4*)(wp + j * 128);
            uint bh[2] = {w.x, w.y};
            uint bl[2] = {w.z, w.w};
#pragma unroll
            for (int m = 0; m < 2; m++) {
                mma_f16(c[m][j], a[m], bh);
                mma_f16(c[m][j], a[m], bl);
            }
        }
    }

#pragma unroll
    for (int m = 0; m < 2; m++) {
        int rg  = rbase + m * 16 + gid;
        int rg8 = rg + 8;
        bool w0 = rg < N_NODES, w8 = rg8 < N_NODES;
#pragma unroll
        for (int j = 0; j < 8; j++) {
            int colh = colhalf * 32 + j * 4 + tig;
            if (w0) {
                __half2 p = __floats2half2_rn(c[m][j][0], c[m][j][1]);
                Hh[(size_t)rg * 64 + colh] = *(uint*)&p;
            }
            if (w8) {
                __half2 p = __floats2half2_rn(c[m][j][2], c[m][j][3]);
                Hh[(size_t)rg8 * 64 + colh] = *(uint*)&p;
            }
        }
    }
}

// ---------------- CSR gather: o = relu(sum H[s]*w + H[d]*recip + b) * gate ----------------
// FINAL=1: write fp32 to out. FINAL=0: write half2-packed to Xh (next GEMM input).
template <int FINAL>
__global__ __launch_bounds__(256) void gather_kernel(const uint* __restrict__ Hh,
                                                     const float* __restrict__ b,
                                                     float* __restrict__ out) {
    int gtid = blockIdx.x * blockDim.x + threadIdx.x;
    int d = gtid >> 5;
    int lane = threadIdx.x & 31;
    if (d >= N_NODES) return;

    int beg = g_rowptr[d];
    int end = g_rowptr[d + 1];

    float rc = g_recip[d];
    uint2 hv = ((const uint2*)(Hh + (size_t)d * 64))[lane];
    float2 a0 = __half22float2(*(__half2*)&hv.x);
    float2 a1 = __half22float2(*(__half2*)&hv.y);
    float4 acc0 = make_float4(a0.x * rc, a0.y * rc, a1.x * rc, a1.y * rc);
    float4 acc1 = make_float4(0.f, 0.f, 0.f, 0.f);

    int e = beg;
    for (; e + 1 < end; e += 2) {
        int s0 = g_csr_src[e];
        int s1 = g_csr_src[e + 1];
        float w0 = g_csr_w[e];
        float w1 = g_csr_w[e + 1];
        uint2 r0 = ((const uint2*)(Hh + (size_t)s0 * 64))[lane];
        uint2 r1 = ((const uint2*)(Hh + (size_t)s1 * 64))[lane];
        float2 h00 = __half22float2(*(__half2*)&r0.x);
        float2 h01 = __half22float2(*(__half2*)&r0.y);
        float2 h10 = __half22float2(*(__half2*)&r1.x);
        float2 h11 = __half22float2(*(__half2*)&r1.y);
        acc0.x += h00.x * w0; acc0.y += h00.y * w0; acc0.z += h01.x * w0; acc0.w += h01.y * w0;
        acc1.x += h10.x * w1; acc1.y += h10.y * w1; acc1.z += h11.x * w1; acc1.w += h11.y * w1;
    }
    if (e < end) {
        int s0 = g_csr_src[e];
        float w0 = g_csr_w[e];
        uint2 r0 = ((const uint2*)(Hh + (size_t)s0 * 64))[lane];
        float2 h00 = __half22float2(*(__half2*)&r0.x);
        float2 h01 = __half22float2(*(__half2*)&r0.y);
        acc0.x += h00.x * w0; acc0.y += h00.y * w0; acc0.z += h01.x * w0; acc0.w += h01.y * w0;
    }

    float4 bv = ((const float4*)b)[lane];
    float4 g = ((const float4*)g_gate)[lane];
    float4 o;
    o.x = fmaxf(acc0.x + acc1.x + bv.x, 0.f) * g.x;
    o.y = fmaxf(acc0.y + acc1.y + bv.y, 0.f) * g.y;
    o.z = fmaxf(acc0.z + acc1.z + bv.z, 0.f) * g.z;
    o.w = fmaxf(acc0.w + acc1.w + bv.w, 0.f) * g.w;

    if (FINAL) {
        ((float4*)(out + (size_t)d * HID))[lane] = o;
    } else {
        __half2 p0 = __floats2half2_rn(o.x, o.y);
        __half2 p1 = __floats2half2_rn(o.z, o.w);
        ((uint2*)(g_Xh + (size_t)d * 64))[lane] = make_uint2(*(uint*)&p0, *(uint*)&p1);
    }
}

// ---------------- launch ----------------
extern "C" void kernel_launch(void* const* d_in, const int* in_sizes, int n_in,
                              void* d_out, int out_size) {
    const float* x   = (const float*)d_in[0];
    const int*   ei  = (const int*)d_in[1];
    const float* ts  = (const float*)d_in[2];
    const float* W0  = (const float*)d_in[3];
    const float* b0  = (const float*)d_in[4];
    const float* W1  = (const float*)d_in[5];
    const float* b1  = (const float*)d_in[6];
    const float* W2  = (const float*)d_in[7];
    const float* b2  = (const float*)d_in[8];
    const float* Wg1 = (const float*)d_in[9];
    const float* bg1 = (const float*)d_in[10];
    const float* Wg2 = (const float*)d_in[11];
    const float* bg2 = (const float*)d_in[12];
    float* out = (float*)d_out;

    const int SMEM = 16384 * 4;   // 64KB
    cudaFuncSetAttribute(gemm_mma_kernel, cudaFuncAttributeMaxDynamicSharedMemorySize, SMEM);

    uint *Hh, *Xh, *Wp;
    int  *cnt;
    cudaGetSymbolAddress((void**)&Hh,  g_Hh);
    cudaGetSymbolAddress((void**)&Xh,  g_Xh);
    cudaGetSymbolAddress((void**)&Wp,  g_Wp);
    cudaGetSymbolAddress((void**)&cnt, g_cnt);

    const int gemm_blocks = (N_NODES + 255) / 256;   // 391
    const int gath_blocks = (N_NODES * 32 + 255) / 256;

    cudaMemsetAsync(cnt, 0, N_NODES * sizeof(int), 0);
    detect_kernel<<<1, 256>>>(ei);                                           // #1
    count_kernel<<<FILL_BLOCKS, 256>>>(ei);                                  // #2
    scanfuse_kernel<<<SCAN_BLOCKS + 97 + CONVX_BLOCKS, 256>>>(
        x, ts, Wg1, bg1, Wg2, bg2, W0, W1, W2);                              // #3
    gemm_mma_kernel<<<gemm_blocks, 512, SMEM>>>(Xh, Wp, Hh);                 // #4 (profiled)
    fill_kernel<<<FILL_BLOCKS, 256>>>(ei);                                   // #5
    gather_kernel<0><<<gath_blocks, 256>>>(Hh, b0, out);
    gemm_mma_kernel<<<gemm_blocks, 512, SMEM>>>(Xh, Wp + 16384, Hh);
    gather_kernel<0><<<gath_blocks, 256>>>(Hh, b1, out);
    gemm_mma_kernel<<<gemm_blocks, 512, SMEM>>>(Xh, Wp + 32768, Hh);
    gather_kernel<1><<<gath_blocks, 256>>>(Hh, b2, out);
}

// round 13
// speedup vs baseline: 1.2798x; 1.0897x over previous
#include <cuda_runtime.h>
#include <cuda_fp16.h>
#include <math.h>

#define N_NODES 100000
#define PAD_ROWS 100096                        // 391*256 grid coverage
#define N_EDGES 600000
#define HID 128
#define SCAN_BLOCKS ((N_NODES + 255) / 256)    // 391
#define FILL_BLOCKS ((N_EDGES + 255) / 256)    // 2344
#define CONVX_BLOCKS ((PAD_ROWS * 8 + 255) / 256)
#define XS_STRIDE 68                           // uints per staged row (272B, pad for LDSM)

typedef unsigned int uint;

// ---------------- device scratch (no allocs allowed) ----------------
__device__ uint  g_Hh[(size_t)N_NODES * 64];    // H = X @ W, half2-packed
__device__ uint  g_Xh[(size_t)PAD_ROWS * 64];   // GEMM input, half2-packed
__device__ float g_dinv[N_NODES];
__device__ float g_recip[N_NODES];
__device__ int   g_cnt[N_NODES];
__device__ int   g_fill[N_NODES];
__device__ int   g_rowptr[N_NODES + 1];
__device__ int   g_csr_src[N_EDGES];
__device__ float g_csr_w[N_EDGES];
__device__ float g_gate[HID];
__device__ int   g_is64;
__device__ uint  g_Wp[3][16384];                // W frags fp16, interleaved {hi0,hi1,lo0,lo1}

__device__ __forceinline__ int edge_src(const int* ei, int e, int is64) {
    return is64 ? ei[2 * e] : ei[e];
}
__device__ __forceinline__ int edge_dst(const int* ei, int e, int is64) {
    return is64 ? ei[2 * (N_EDGES + e)] : ei[N_EDGES + e];
}

__device__ __forceinline__ void cvt_hilo_h(uint& hi, uint& lo, float2 v) {
    __half2 h = __floats2half2_rn(v.x, v.y);
    float hx = __half2float(__low2half(h));
    float hy = __half2float(__high2half(h));
    __half2 l = __floats2half2_rn(v.x - hx, v.y - hy);
    hi = *(uint*)&h;
    lo = *(uint*)&l;
}

// ---------------- K1: dtype detect ----------------
__global__ void detect_kernel(const int* __restrict__ ei) {
    __shared__ int any_nz;
    if (threadIdx.x == 0) any_nz = 0;
    __syncthreads();
    int local = 0;
    for (int j = threadIdx.x; j < 4096; j += 256) local |= ei[2 * j + 1];
    if (local) atomicOr(&any_nz, 1);
    __syncthreads();
    if (threadIdx.x == 0) g_is64 = (any_nz == 0) ? 1 : 0;
}

// ---------------- K2: count in-degrees ----------------
__global__ void count_kernel(const int* __restrict__ ei) {
    int e = blockIdx.x * blockDim.x + threadIdx.x;
    if (e >= N_EDGES) return;
    atomicAdd(&g_cnt[edge_dst(ei, e, g_is64)], 1);
}

// ---------------- K3: fused scan + deg + rowptr + gate + convW + convX ----------------
__global__ void scanfuse_kernel(const float* __restrict__ x,
                                const float* __restrict__ t,
                                const float* __restrict__ Wg1, const float* __restrict__ bg1,
                                const float* __restrict__ Wg2, const float* __restrict__ bg2,
                                const float* __restrict__ W0, const float* __restrict__ W1,
                                const float* __restrict__ W2) {
    if (blockIdx.x >= SCAN_BLOCKS + 97) {
        int id = (blockIdx.x - (SCAN_BLOCKS + 97)) * 256 + threadIdx.x;
        int row = id >> 3, seg = id & 7;
        if (row >= PAD_ROWS) return;
        uint4 u0, u1;
        if (row < N_NODES) {
            const float4* xr = (const float4*)(x + (size_t)row * HID + seg * 16);
            float4 f0 = xr[0], f1 = xr[1], f2 = xr[2], f3 = xr[3];
            __half2 h0 = __floats2half2_rn(f0.x, f0.y), h1 = __floats2half2_rn(f0.z, f0.w);
            __half2 h2 = __floats2half2_rn(f1.x, f1.y), h3 = __floats2half2_rn(f1.z, f1.w);
            __half2 h4 = __floats2half2_rn(f2.x, f2.y), h5 = __floats2half2_rn(f2.z, f2.w);
            __half2 h6 = __floats2half2_rn(f3.x, f3.y), h7 = __floats2half2_rn(f3.z, f3.w);
            u0 = make_uint4(*(uint*)&h0, *(uint*)&h1, *(uint*)&h2, *(uint*)&h3);
            u1 = make_uint4(*(uint*)&h4, *(uint*)&h5, *(uint*)&h6, *(uint*)&h7);
        } else {
            u0 = make_uint4(0, 0, 0, 0);
            u1 = make_uint4(0, 0, 0, 0);
        }
        uint4* dst = (uint4*)(g_Xh + (size_t)row * 64 + seg * 8);
        dst[0] = u0;
        dst[1] = u1;
        return;
    }
    if (blockIdx.x >= SCAN_BLOCKS) {
        int cb = blockIdx.x - SCAN_BLOCKS;
        if (cb == 96) {
            __shared__ float h1s[HID];
            int j = threadIdx.x;
            if (j < HID) h1s[j] = tanhf(t[0] * Wg1[j] + bg1[j]);
            __syncthreads();
            if (j < HID) {
                float s = bg2[j];
#pragma unroll 8
                for (int k = 0; k < HID; k++) s += h1s[k] * Wg2[k * HID + j];
                g_gate[j] = 1.0f / (1.0f + expf(-s));
            }
            return;
        }
        int layer = cb >> 5;
        const float* W = (layer == 0) ? W0 : ((layer == 1) ? W1 : W2);
        uint* Wp = g_Wp[layer];
        int tt = (cb & 31) * 256 + threadIdx.x;
        int r = tt & 1, lane = (tt >> 1) & 31, nt = (tt >> 6) & 15, kc = tt >> 10;
        int k = kc * 16 + r * 8 + (lane & 3) * 2;
        int n = nt * 8 + (lane >> 2);
        float w0 = W[k * HID + n];
        float w1 = W[(k + 1) * HID + n];
        uint hi, lo;
        cvt_hilo_h(hi, lo, make_float2(w0, w1));
        int base = (tt >> 1) * 4;
        Wp[base + r]     = hi;
        Wp[base + 2 + r] = lo;
        return;
    }

    __shared__ int sh[256];
    __shared__ int pref[256];
    int tx = threadIdx.x;
    int bid = blockIdx.x;
    int base = bid * 256;

    int local = 0;
    for (int j = tx; j < base; j += 256) local += g_cnt[j];
    pref[tx] = local;

    int i = base + tx;
    int c = (i < N_NODES) ? g_cnt[i] : 0;
    if (i < N_NODES) {
        float deg = (float)c + 1.0f;
        g_dinv[i]  = rsqrtf(deg);
        g_recip[i] = 1.0f / deg;
        g_fill[i]  = 0;
    }
    __syncthreads();
#pragma unroll
    for (int s = 128; s > 0; s >>= 1) {
        if (tx < s) pref[tx] += pref[tx + s];
        __syncthreads();
    }
    int blockoff = pref[0];

    sh[tx] = c;
    __syncthreads();
#pragma unroll
    for (int off = 1; off < 256; off <<= 1) {
        int v = (tx >= off) ? sh[tx - off] : 0;
        __syncthreads();
        sh[tx] += v;
        __syncthreads();
    }
    if (i < N_NODES) g_rowptr[i] = blockoff + sh[tx] - c;
    if (i == N_NODES - 1) g_rowptr[N_NODES] = N_EDGES;
}

// ---------------- K5: CSR fill (+ edge weights) ----------------
__global__ void fill_kernel(const int* __restrict__ ei) {
    int e = blockIdx.x * blockDim.x + threadIdx.x;
    if (e >= N_EDGES) return;
    int is64 = g_is64;
    int s = edge_src(ei, e, is64);
    int d = edge_dst(ei, e, is64);
    int pos = g_rowptr[d] + atomicAdd(&g_fill[d], 1);
    g_csr_src[pos] = s;
    g_csr_w[pos] = g_dinv[s] * g_dinv[d];
}

// ---------------- MMA / LDSM helpers ----------------
__device__ __forceinline__ void mma_f16(float* c, const uint* a, uint b0, uint b1) {
    asm volatile(
        "mma.sync.aligned.m16n8k16.row.col.f32.f16.f16.f32 "
        "{%0,%1,%2,%3}, {%4,%5,%6,%7}, {%8,%9}, {%0,%1,%2,%3};"
        : "+f"(c[0]), "+f"(c[1]), "+f"(c[2]), "+f"(c[3])
        : "r"(a[0]), "r"(a[1]), "r"(a[2]), "r"(a[3]), "r"(b0), "r"(b1));
}

__device__ __forceinline__ void ldsm_x4(uint* r, uint saddr) {
    asm volatile(
        "ldmatrix.sync.aligned.m8n8.x4.shared.b16 {%0,%1,%2,%3}, [%4];"
        : "=r"(r[0]), "=r"(r[1]), "=r"(r[2]), "=r"(r[3])
        : "r"(saddr));
}

// ---------------- GEMM: Hh = Xh @ W  (512 thr; X-tile staged in smem; LDSM A-frags) ----------------
__global__ __launch_bounds__(512) void gemm_mma_kernel(
    const uint* __restrict__ Xh, const uint* __restrict__ Wp,
    uint* __restrict__ Hh) {
    extern __shared__ uint smem[];
    uint* sWp = smem;                   // 16384 uints = 64KB
    uint* sX  = smem + 16384;           // 256 * 68 uints = 69632B

    int tx = threadIdx.x;
#pragma unroll
    for (int i = tx; i < 4096; i += 512)
        ((uint4*)sWp)[i] = ((const uint4*)Wp)[i];

    // stage X tile: 256 rows x 64 uints, coalesced LDG.128, padded rows in smem
    size_t rowbase = (size_t)blockIdx.x * 256;
    const uint4* src = (const uint4*)(Xh + rowbase * 64);
#pragma unroll
    for (int i = 0; i < 8; i++) {
        int idx = tx + i * 512;          // 0..4095
        int row = idx >> 4, c16 = idx & 15;
        uint4 v = src[idx];
        *(uint4*)(sX + row * XS_STRIDE + c16 * 4) = v;
    }
    __syncthreads();

    int warp = tx >> 5, lane = tx & 31;
    int gid = lane >> 2, tig = lane & 3;
    int colhalf = warp & 1;
    int wrow = (warp >> 1) * 32;         // local row base (warp = 32 rows x 64 cols)

    // LDSM source addresses: lanes 0-15 -> rows 0-15 (k bytes +0); 16-31 -> rows 0-15 (+16B)
    int lrow = (lane & 15);
    int loff = (lane >> 4) * 16;         // bytes
    uint sxb = (uint)__cvta_generic_to_shared(sX);
    uint sa0 = sxb + ((wrow + lrow) * XS_STRIDE) * 4 + loff;
    uint sa1 = sa0 + 16 * XS_STRIDE * 4;

    float c[2][8][4];
#pragma unroll
    for (int m = 0; m < 2; m++)
#pragma unroll
        for (int j = 0; j < 8; j++)
#pragma unroll
            for (int r = 0; r < 4; r++) c[m][j][r] = 0.f;

#pragma unroll
    for (int kc = 0; kc < 8; kc++) {
        uint a0[4], a1[4];
        ldsm_x4(a0, sa0 + kc * 32);
        ldsm_x4(a1, sa1 + kc * 32);

        const uint* wp = sWp + ((kc * 16 + colhalf * 8) * 32 + lane) * 4;
#pragma unroll
        for (int j = 0; j < 8; j++) {
            uint4 w = *(const uint4*)(wp + j * 128);
            mma_f16(c[0][j], a0, w.x, w.y);
            mma_f16(c[0][j], a0, w.z, w.w);
            mma_f16(c[1][j], a1, w.x, w.y);
            mma_f16(c[1][j], a1, w.z, w.w);
        }
    }

    int rbase = blockIdx.x * 256 + wrow;
#pragma unroll
    for (int m = 0; m < 2; m++) {
        int rg  = rbase + m * 16 + gid;
        int rg8 = rg + 8;
        bool w0 = rg < N_NODES, w8 = rg8 < N_NODES;
#pragma unroll
        for (int j = 0; j < 8; j++) {
            int colh = colhalf * 32 + j * 4 + tig;
            if (w0) {
                __half2 p = __floats2half2_rn(c[m][j][0], c[m][j][1]);
                Hh[(size_t)rg * 64 + colh] = *(uint*)&p;
            }
            if (w8) {
                __half2 p = __floats2half2_rn(c[m][j][2], c[m][j][3]);
                Hh[(size_t)rg8 * 64 + colh] = *(uint*)&p;
            }
        }
    }
}

// ---------------- CSR gather: half-warp per node, uint4 per lane ----------------
// o = relu(sum H[s]*w + H[d]*recip + b) * gate
// FINAL=1: write fp32 to out. FINAL=0: write half2-packed to Xh.
template <int FINAL>
__global__ __launch_bounds__(256) void gather_kernel(const uint* __restrict__ Hh,
                                                     const float* __restrict__ b,
                                                     float* __restrict__ out) {
    int gtid = blockIdx.x * blockDim.x + threadIdx.x;
    int d = gtid >> 4;
    int lane = threadIdx.x & 15;
    if (d >= N_NODES) return;

    int beg = g_rowptr[d];
    int end = g_rowptr[d + 1];
    const uint4* Hr = (const uint4*)Hh;      // 16 uint4 per row

    float acc0[8], acc1[8];
    {
        float rc = g_recip[d];
        uint4 hv = Hr[(size_t)d * 16 + lane];
        const __half2* hp = (const __half2*)&hv;
#pragma unroll
        for (int q = 0; q < 4; q++) {
            float2 f = __half22float2(hp[q]);
            acc0[q * 2]     = f.x * rc;
            acc0[q * 2 + 1] = f.y * rc;
            acc1[q * 2]     = 0.f;
            acc1[q * 2 + 1] = 0.f;
        }
    }

    int e = beg;
    for (; e + 1 < end; e += 2) {
        int s0 = g_csr_src[e];
        int s1 = g_csr_src[e + 1];
        float w0 = g_csr_w[e];
        float w1 = g_csr_w[e + 1];
        uint4 r0 = Hr[(size_t)s0 * 16 + lane];
        uint4 r1 = Hr[(size_t)s1 * 16 + lane];
        const __half2* q0 = (const __half2*)&r0;
        const __half2* q1 = (const __half2*)&r1;
#pragma unroll
        for (int q = 0; q < 4; q++) {
            float2 f0 = __half22float2(q0[q]);
            float2 f1 = __half22float2(q1[q]);
            acc0[q * 2]     += f0.x * w0;
            acc0[q * 2 + 1] += f0.y * w0;
            acc1[q * 2]     += f1.x * w1;
            acc1[q * 2 + 1] += f1.y * w1;
        }
    }
    if (e < end) {
        int s0 = g_csr_src[e];
        float w0 = g_csr_w[e];
        uint4 r0 = Hr[(size_t)s0 * 16 + lane];
        const __half2* q0 = (const __half2*)&r0;
#pragma unroll
        for (int q = 0; q < 4; q++) {
            float2 f0 = __half22float2(q0[q]);
            acc0[q * 2]     += f0.x * w0;
            acc0[q * 2 + 1] += f0.y * w0;
        }
    }

    float4 bv0 = ((const float4*)b)[lane * 2];
    float4 bv1 = ((const float4*)b)[lane * 2 + 1];
    float4 g0  = ((const float4*)g_gate)[lane * 2];
    float4 g1  = ((const float4*)g_gate)[lane * 2 + 1];
    float bb[8] = {bv0.x, bv0.y, bv0.z, bv0.w, bv1.x, bv1.y, bv1.z, bv1.w};
    float gg[8] = {g0.x,  g0.y,  g0.z,  g0.w,  g1.x,  g1.y,  g1.z,  g1.w};

    float o[8];
#pragma unroll
    for (int q = 0; q < 8; q++)
        o[q] = fmaxf(acc0[q] + acc1[q] + bb[q], 0.f) * gg[q];

    if (FINAL) {
        float4* orow = (float4*)(out + (size_t)d * HID);
        orow[lane * 2]     = make_float4(o[0], o[1], o[2], o[3]);
        orow[lane * 2 + 1] = make_float4(o[4], o[5], o[6], o[7]);
    } else {
        __half2 p0 = __floats2half2_rn(o[0], o[1]);
        __half2 p1 = __floats2half2_rn(o[2], o[3]);
        __half2 p2 = __floats2half2_rn(o[4], o[5]);
        __half2 p3 = __floats2half2_rn(o[6], o[7]);
        ((uint4*)g_Xh)[(size_t)d * 16 + lane] =
            make_uint4(*(uint*)&p0, *(uint*)&p1, *(uint*)&p2, *(uint*)&p3);
    }
}

// ---------------- launch ----------------
extern "C" void kernel_launch(void* const* d_in, const int* in_sizes, int n_in,
                              void* d_out, int out_size) {
    const float* x   = (const float*)d_in[0];
    const int*   ei  = (const int*)d_in[1];
    const float* ts  = (const float*)d_in[2];
    const float* W0  = (const float*)d_in[3];
    const float* b0  = (const float*)d_in[4];
    const float* W1  = (const float*)d_in[5];
    const float* b1  = (const float*)d_in[6];
    const float* W2  = (const float*)d_in[7];
    const float* b2  = (const float*)d_in[8];
    const float* Wg1 = (const float*)d_in[9];
    const float* bg1 = (const float*)d_in[10];
    const float* Wg2 = (const float*)d_in[11];
    const float* bg2 = (const float*)d_in[12];
    float* out = (float*)d_out;

    const int SMEM = (16384 + 256 * XS_STRIDE) * 4;   // 64KB + 68KB = 135168B
    cudaFuncSetAttribute(gemm_mma_kernel, cudaFuncAttributeMaxDynamicSharedMemorySize, SMEM);

    uint *Hh, *Xh, *Wp;
    int  *cnt;
    cudaGetSymbolAddress((void**)&Hh,  g_Hh);
    cudaGetSymbolAddress((void**)&Xh,  g_Xh);
    cudaGetSymbolAddress((void**)&Wp,  g_Wp);
    cudaGetSymbolAddress((void**)&cnt, g_cnt);

    const int gemm_blocks = (N_NODES + 255) / 256;         // 391
    const int gath_blocks = (N_NODES * 16 + 255) / 256;    // 6250

    cudaMemsetAsync(cnt, 0, N_NODES * sizeof(int), 0);
    detect_kernel<<<1, 256>>>(ei);                                           // #1
    count_kernel<<<FILL_BLOCKS, 256>>>(ei);                                  // #2
    scanfuse_kernel<<<SCAN_BLOCKS + 97 + CONVX_BLOCKS, 256>>>(
        x, ts, Wg1, bg1, Wg2, bg2, W0, W1, W2);                              // #3
    gemm_mma_kernel<<<gemm_blocks, 512, SMEM>>>(Xh, Wp, Hh);                 // #4 (profiled)
    fill_kernel<<<FILL_BLOCKS, 256>>>(ei);                                   // #5
    gather_kernel<0><<<gath_blocks, 256>>>(Hh, b0, out);
    gemm_mma_kernel<<<gemm_blocks, 512, SMEM>>>(Xh, Wp + 16384, Hh);
    gather_kernel<0><<<gath_blocks, 256>>>(Hh, b1, out);
    gemm_mma_kernel<<<gemm_blocks, 512, SMEM>>>(Xh, Wp + 32768, Hh);
    gather_kernel<1><<<gath_blocks, 256>>>(Hh, b2, out);
}

// round 14
// speedup vs baseline: 1.3941x; 1.0893x over previous
#include <cuda_runtime.h>
#include <cuda_fp16.h>
#include <math.h>

#define N_NODES 100000
#define PAD_ROWS 100096                        // 391*256 grid coverage
#define N_EDGES 600000
#define HID 128
#define SCAN_BLOCKS ((N_NODES + 255) / 256)    // 391
#define FILL_BLOCKS ((N_EDGES + 255) / 256)    // 2344
#define CONVX_BLOCKS ((PAD_ROWS * 8 + 255) / 256)
#define XS_STRIDE 68                           // uints per staged row (272B, pad for LDSM)

typedef unsigned int uint;

// ---------------- device scratch (no allocs allowed) ----------------
__device__ uint  g_Hh[(size_t)N_NODES * 64];    // H = X @ W, half2-packed
__device__ uint  g_Xh[(size_t)PAD_ROWS * 64];   // GEMM input, half2-packed
__device__ float g_dinv[N_NODES];
__device__ float g_recip[N_NODES];
__device__ int   g_cnt[N_NODES];
__device__ int   g_fill[N_NODES];
__device__ int   g_rowptr[N_NODES + 1];
__device__ int   g_csr_src[N_EDGES];
__device__ float g_csr_w[N_EDGES];
__device__ float g_gate[HID];
__device__ int   g_is64;
__device__ uint  g_Wp[3][8192];                 // W frags fp16 (single precision level)

__device__ __forceinline__ int edge_src(const int* ei, int e, int is64) {
    return is64 ? ei[2 * e] : ei[e];
}
__device__ __forceinline__ int edge_dst(const int* ei, int e, int is64) {
    return is64 ? ei[2 * (N_EDGES + e)] : ei[N_EDGES + e];
}

// ---------------- K1: dtype detect ----------------
__global__ void detect_kernel(const int* __restrict__ ei) {
    __shared__ int any_nz;
    if (threadIdx.x == 0) any_nz = 0;
    __syncthreads();
    int local = 0;
    for (int j = threadIdx.x; j < 4096; j += 256) local |= ei[2 * j + 1];
    if (local) atomicOr(&any_nz, 1);
    __syncthreads();
    if (threadIdx.x == 0) g_is64 = (any_nz == 0) ? 1 : 0;
}

// ---------------- K2: count in-degrees ----------------
__global__ void count_kernel(const int* __restrict__ ei) {
    int e = blockIdx.x * blockDim.x + threadIdx.x;
    if (e >= N_EDGES) return;
    atomicAdd(&g_cnt[edge_dst(ei, e, g_is64)], 1);
}

// ---------------- K3: fused scan + deg + rowptr + gate + convW + convX ----------------
__global__ void scanfuse_kernel(const float* __restrict__ x,
                                const float* __restrict__ t,
                                const float* __restrict__ Wg1, const float* __restrict__ bg1,
                                const float* __restrict__ Wg2, const float* __restrict__ bg2,
                                const float* __restrict__ W0, const float* __restrict__ W1,
                                const float* __restrict__ W2) {
    if (blockIdx.x >= SCAN_BLOCKS + 97) {
        int id = (blockIdx.x - (SCAN_BLOCKS + 97)) * 256 + threadIdx.x;
        int row = id >> 3, seg = id & 7;
        if (row >= PAD_ROWS) return;
        uint4 u0, u1;
        if (row < N_NODES) {
            const float4* xr = (const float4*)(x + (size_t)row * HID + seg * 16);
            float4 f0 = xr[0], f1 = xr[1], f2 = xr[2], f3 = xr[3];
            __half2 h0 = __floats2half2_rn(f0.x, f0.y), h1 = __floats2half2_rn(f0.z, f0.w);
            __half2 h2 = __floats2half2_rn(f1.x, f1.y), h3 = __floats2half2_rn(f1.z, f1.w);
            __half2 h4 = __floats2half2_rn(f2.x, f2.y), h5 = __floats2half2_rn(f2.z, f2.w);
            __half2 h6 = __floats2half2_rn(f3.x, f3.y), h7 = __floats2half2_rn(f3.z, f3.w);
            u0 = make_uint4(*(uint*)&h0, *(uint*)&h1, *(uint*)&h2, *(uint*)&h3);
            u1 = make_uint4(*(uint*)&h4, *(uint*)&h5, *(uint*)&h6, *(uint*)&h7);
        } else {
            u0 = make_uint4(0, 0, 0, 0);
            u1 = make_uint4(0, 0, 0, 0);
        }
        uint4* dst = (uint4*)(g_Xh + (size_t)row * 64 + seg * 8);
        dst[0] = u0;
        dst[1] = u1;
        return;
    }
    if (blockIdx.x >= SCAN_BLOCKS) {
        int cb = blockIdx.x - SCAN_BLOCKS;
        if (cb == 96) {
            __shared__ float h1s[HID];
            int j = threadIdx.x;
            if (j < HID) h1s[j] = tanhf(t[0] * Wg1[j] + bg1[j]);
            __syncthreads();
            if (j < HID) {
                float s = bg2[j];
#pragma unroll 8
                for (int k = 0; k < HID; k++) s += h1s[k] * Wg2[k * HID + j];
                g_gate[j] = 1.0f / (1.0f + expf(-s));
            }
            return;
        }
        int layer = cb >> 5;
        const float* W = (layer == 0) ? W0 : ((layer == 1) ? W1 : W2);
        uint* Wp = g_Wp[layer];
        int tt = (cb & 31) * 256 + threadIdx.x;
        int r = tt & 1, lane = (tt >> 1) & 31, nt = (tt >> 6) & 15, kc = tt >> 10;
        int k = kc * 16 + r * 8 + (lane & 3) * 2;
        int n = nt * 8 + (lane >> 2);
        __half2 h = __floats2half2_rn(W[k * HID + n], W[(k + 1) * HID + n]);
        Wp[tt] = *(uint*)&h;
        return;
    }

    __shared__ int sh[256];
    __shared__ int pref[256];
    int tx = threadIdx.x;
    int bid = blockIdx.x;
    int base = bid * 256;

    int local = 0;
    for (int j = tx; j < base; j += 256) local += g_cnt[j];
    pref[tx] = local;

    int i = base + tx;
    int c = (i < N_NODES) ? g_cnt[i] : 0;
    if (i < N_NODES) {
        float deg = (float)c + 1.0f;
        g_dinv[i]  = rsqrtf(deg);
        g_recip[i] = 1.0f / deg;
        g_fill[i]  = 0;
    }
    __syncthreads();
#pragma unroll
    for (int s = 128; s > 0; s >>= 1) {
        if (tx < s) pref[tx] += pref[tx + s];
        __syncthreads();
    }
    int blockoff = pref[0];

    sh[tx] = c;
    __syncthreads();
#pragma unroll
    for (int off = 1; off < 256; off <<= 1) {
        int v = (tx >= off) ? sh[tx - off] : 0;
        __syncthreads();
        sh[tx] += v;
        __syncthreads();
    }
    if (i < N_NODES) g_rowptr[i] = blockoff + sh[tx] - c;
    if (i == N_NODES - 1) g_rowptr[N_NODES] = N_EDGES;
}

// ---------------- K5: CSR fill (+ edge weights) ----------------
__global__ void fill_kernel(const int* __restrict__ ei) {
    int e = blockIdx.x * blockDim.x + threadIdx.x;
    if (e >= N_EDGES) return;
    int is64 = g_is64;
    int s = edge_src(ei, e, is64);
    int d = edge_dst(ei, e, is64);
    int pos = g_rowptr[d] + atomicAdd(&g_fill[d], 1);
    g_csr_src[pos] = s;
    g_csr_w[pos] = g_dinv[s] * g_dinv[d];
}

// ---------------- MMA / LDSM helpers ----------------
__device__ __forceinline__ void mma_f16(float* c, const uint* a, uint b0, uint b1) {
    asm volatile(
        "mma.sync.aligned.m16n8k16.row.col.f32.f16.f16.f32 "
        "{%0,%1,%2,%3}, {%4,%5,%6,%7}, {%8,%9}, {%0,%1,%2,%3};"
        : "+f"(c[0]), "+f"(c[1]), "+f"(c[2]), "+f"(c[3])
        : "r"(a[0]), "r"(a[1]), "r"(a[2]), "r"(a[3]), "r"(b0), "r"(b1));
}

__device__ __forceinline__ void ldsm_x4(uint* r, uint saddr) {
    asm volatile(
        "ldmatrix.sync.aligned.m8n8.x4.shared.b16 {%0,%1,%2,%3}, [%4];"
        : "=r"(r[0]), "=r"(r[1]), "=r"(r[2]), "=r"(r[3])
        : "r"(saddr));
}

// ---------------- GEMM: Hh = Xh @ W  (512 thr; smem X + LDSM; single-fp16 W) ----------------
__global__ __launch_bounds__(512) void gemm_mma_kernel(
    const uint* __restrict__ Xh, const uint* __restrict__ Wp,
    uint* __restrict__ Hh) {
    extern __shared__ uint smem[];
    uint* sWp = smem;                   // 8192 uints = 32KB
    uint* sX  = smem + 8192;            // 256 * 68 uints = 69632B

    int tx = threadIdx.x;
#pragma unroll
    for (int i = tx; i < 2048; i += 512)
        ((uint4*)sWp)[i] = ((const uint4*)Wp)[i];

    // stage X tile: 256 rows x 64 uints, coalesced LDG.128
    size_t rowbase = (size_t)blockIdx.x * 256;
    const uint4* src = (const uint4*)(Xh + rowbase * 64);
#pragma unroll
    for (int i = 0; i < 8; i++) {
        int idx = tx + i * 512;          // 0..4095
        int row = idx >> 4, c16 = idx & 15;
        uint4 v = src[idx];
        *(uint4*)(sX + row * XS_STRIDE + c16 * 4) = v;
    }
    __syncthreads();

    int warp = tx >> 5, lane = tx & 31;
    int gid = lane >> 2, tig = lane & 3;
    int colhalf = warp & 1;
    int wrow = (warp >> 1) * 32;         // warp = 32 rows x 64 cols

    int lrow = (lane & 15);
    int loff = (lane >> 4) * 16;         // bytes
    uint sxb = (uint)__cvta_generic_to_shared(sX);
    uint sa0 = sxb + ((wrow + lrow) * XS_STRIDE) * 4 + loff;
    uint sa1 = sa0 + 16 * XS_STRIDE * 4;

    float c[2][8][4];
#pragma unroll
    for (int m = 0; m < 2; m++)
#pragma unroll
        for (int j = 0; j < 8; j++)
#pragma unroll
            for (int r = 0; r < 4; r++) c[m][j][r] = 0.f;

#pragma unroll
    for (int kc = 0; kc < 8; kc++) {
        uint a0[4], a1[4];
        ldsm_x4(a0, sa0 + kc * 32);
        ldsm_x4(a1, sa1 + kc * 32);

        const uint* wp = sWp + ((kc * 16 + colhalf * 8) * 32 + lane) * 2;
#pragma unroll
        for (int j = 0; j < 8; j++) {
            uint2 w = *(const uint2*)(wp + j * 64);
            mma_f16(c[0][j], a0, w.x, w.y);
            mma_f16(c[1][j], a1, w.x, w.y);
        }
    }

    int rbase = blockIdx.x * 256 + wrow;
#pragma unroll
    for (int m = 0; m < 2; m++) {
        int rg  = rbase + m * 16 + gid;
        int rg8 = rg + 8;
        bool w0 = rg < N_NODES, w8 = rg8 < N_NODES;
#pragma unroll
        for (int j = 0; j < 8; j++) {
            int colh = colhalf * 32 + j * 4 + tig;
            if (w0) {
                __half2 p = __floats2half2_rn(c[m][j][0], c[m][j][1]);
                Hh[(size_t)rg * 64 + colh] = *(uint*)&p;
            }
            if (w8) {
                __half2 p = __floats2half2_rn(c[m][j][2], c[m][j][3]);
                Hh[(size_t)rg8 * 64 + colh] = *(uint*)&p;
            }
        }
    }
}

// ---------------- CSR gather: half-warp per node, uint4 per lane ----------------
template <int FINAL>
__global__ __launch_bounds__(256) void gather_kernel(const uint* __restrict__ Hh,
                                                     const float* __restrict__ b,
                                                     float* __restrict__ out) {
    int gtid = blockIdx.x * blockDim.x + threadIdx.x;
    int d = gtid >> 4;
    int lane = threadIdx.x & 15;
    if (d >= N_NODES) return;

    int beg = g_rowptr[d];
    int end = g_rowptr[d + 1];
    const uint4* Hr = (const uint4*)Hh;      // 16 uint4 per row

    float acc0[8], acc1[8];
    {
        float rc = g_recip[d];
        uint4 hv = Hr[(size_t)d * 16 + lane];
        const __half2* hp = (const __half2*)&hv;
#pragma unroll
        for (int q = 0; q < 4; q++) {
            float2 f = __half22float2(hp[q]);
            acc0[q * 2]     = f.x * rc;
            acc0[q * 2 + 1] = f.y * rc;
            acc1[q * 2]     = 0.f;
            acc1[q * 2 + 1] = 0.f;
        }
    }

    int e = beg;
    for (; e + 1 < end; e += 2) {
        int s0 = g_csr_src[e];
        int s1 = g_csr_src[e + 1];
        float w0 = g_csr_w[e];
        float w1 = g_csr_w[e + 1];
        uint4 r0 = Hr[(size_t)s0 * 16 + lane];
        uint4 r1 = Hr[(size_t)s1 * 16 + lane];
        const __half2* q0 = (const __half2*)&r0;
        const __half2* q1 = (const __half2*)&r1;
#pragma unroll
        for (int q = 0; q < 4; q++) {
            float2 f0 = __half22float2(q0[q]);
            float2 f1 = __half22float2(q1[q]);
            acc0[q * 2]     += f0.x * w0;
            acc0[q * 2 + 1] += f0.y * w0;
            acc1[q * 2]     += f1.x * w1;
            acc1[q * 2 + 1] += f1.y * w1;
        }
    }
    if (e < end) {
        int s0 = g_csr_src[e];
        float w0 = g_csr_w[e];
        uint4 r0 = Hr[(size_t)s0 * 16 + lane];
        const __half2* q0 = (const __half2*)&r0;
#pragma unroll
        for (int q = 0; q < 4; q++) {
            float2 f0 = __half22float2(q0[q]);
            acc0[q * 2]     += f0.x * w0;
            acc0[q * 2 + 1] += f0.y * w0;
        }
    }

    float4 bv0 = ((const float4*)b)[lane * 2];
    float4 bv1 = ((const float4*)b)[lane * 2 + 1];
    float4 g0  = ((const float4*)g_gate)[lane * 2];
    float4 g1  = ((const float4*)g_gate)[lane * 2 + 1];
    float bb[8] = {bv0.x, bv0.y, bv0.z, bv0.w, bv1.x, bv1.y, bv1.z, bv1.w};
    float gg[8] = {g0.x,  g0.y,  g0.z,  g0.w,  g1.x,  g1.y,  g1.z,  g1.w};

    float o[8];
#pragma unroll
    for (int q = 0; q < 8; q++)
        o[q] = fmaxf(acc0[q] + acc1[q] + bb[q], 0.f) * gg[q];

    if (FINAL) {
        float4* orow = (float4*)(out + (size_t)d * HID);
        orow[lane * 2]     = make_float4(o[0], o[1], o[2], o[3]);
        orow[lane * 2 + 1] = make_float4(o[4], o[5], o[6], o[7]);
    } else {
        __half2 p0 = __floats2half2_rn(o[0], o[1]);
        __half2 p1 = __floats2half2_rn(o[2], o[3]);
        __half2 p2 = __floats2half2_rn(o[4], o[5]);
        __half2 p3 = __floats2half2_rn(o[6], o[7]);
        ((uint4*)g_Xh)[(size_t)d * 16 + lane] =
            make_uint4(*(uint*)&p0, *(uint*)&p1, *(uint*)&p2, *(uint*)&p3);
    }
}

// ---------------- launch ----------------
extern "C" void kernel_launch(void* const* d_in, const int* in_sizes, int n_in,
                              void* d_out, int out_size) {
    const float* x   = (const float*)d_in[0];
    const int*   ei  = (const int*)d_in[1];
    const float* ts  = (const float*)d_in[2];
    const float* W0  = (const float*)d_in[3];
    const float* b0  = (const float*)d_in[4];
    const float* W1  = (const float*)d_in[5];
    const float* b1  = (const float*)d_in[6];
    const float* W2  = (const float*)d_in[7];
    const float* b2  = (const float*)d_in[8];
    const float* Wg1 = (const float*)d_in[9];
    const float* bg1 = (const float*)d_in[10];
    const float* Wg2 = (const float*)d_in[11];
    const float* bg2 = (const float*)d_in[12];
    float* out = (float*)d_out;

    const int SMEM = (8192 + 256 * XS_STRIDE) * 4;   // 32KB + 68KB = 102400B
    cudaFuncSetAttribute(gemm_mma_kernel, cudaFuncAttributeMaxDynamicSharedMemorySize, SMEM);

    uint *Hh, *Xh, *Wp;
    int  *cnt;
    cudaGetSymbolAddress((void**)&Hh,  g_Hh);
    cudaGetSymbolAddress((void**)&Xh,  g_Xh);
    cudaGetSymbolAddress((void**)&Wp,  g_Wp);
    cudaGetSymbolAddress((void**)&cnt, g_cnt);

    const int gemm_blocks = (N_NODES + 255) / 256;         // 391
    const int gath_blocks = (N_NODES * 16 + 255) / 256;    // 6250

    cudaMemsetAsync(cnt, 0, N_NODES * sizeof(int), 0);
    detect_kernel<<<1, 256>>>(ei);                                           // #1
    count_kernel<<<FILL_BLOCKS, 256>>>(ei);                                  // #2
    scanfuse_kernel<<<SCAN_BLOCKS + 97 + CONVX_BLOCKS, 256>>>(
        x, ts, Wg1, bg1, Wg2, bg2, W0, W1, W2);                              // #3
    gemm_mma_kernel<<<gemm_blocks, 512, SMEM>>>(Xh, Wp, Hh);                 // #4 (profiled)
    fill_kernel<<<FILL_BLOCKS, 256>>>(ei);                                   // #5
    gather_kernel<0><<<gath_blocks, 256>>>(Hh, b0, out);
    gemm_mma_kernel<<<gemm_blocks, 512, SMEM>>>(Xh, Wp + 8192, Hh);
    gather_kernel<0><<<gath_blocks, 256>>>(Hh, b1, out);
    gemm_mma_kernel<<<gemm_blocks, 512, SMEM>>>(Xh, Wp + 16384, Hh);
    gather_kernel<1><<<gath_blocks, 256>>>(Hh, b2, out);
}